// round 1
// baseline (speedup 1.0000x reference)
#include <cuda_runtime.h>

// GumbelSinkhorn: B=128, N=512 (agents/rows), M=512 (tasks/cols), tau=1, 5 iters.
// x = softmax(x, axis=2)*mask ; x = softmax(x, axis=1)*mask  (x5)
// Buffer invariant: g_E holds exp(x_k) over the active [na, nt] region.
// g_rsum / g_csum hold RECIPROCAL sums of exp over rows / cols.

#define BB 128
#define NN 512
#define MM 512

__device__ float g_E[(size_t)BB * NN * MM];   // 128 MB scratch
__device__ float g_rsum[BB * NN];             // 1 / sum_c exp(x[r,c])
__device__ float g_csum[BB * MM];             // 1 / sum_r exp(x[r,c])

__device__ __forceinline__ float warp_sum(float v) {
    v += __shfl_xor_sync(0xffffffffu, v, 16);
    v += __shfl_xor_sync(0xffffffffu, v, 8);
    v += __shfl_xor_sync(0xffffffffu, v, 4);
    v += __shfl_xor_sync(0xffffffffu, v, 2);
    v += __shfl_xor_sync(0xffffffffu, v, 1);
    return v;
}

// E0 = exp(logits) over active region; rsum = 1/rowsum(E0).
// Row strips of 32: grid(16, B), block 256 (8 warps, warp handles 4 rows).
__global__ void init_kernel(const float* __restrict__ logits,
                            const int* __restrict__ fa,
                            const int* __restrict__ ta) {
    int b = blockIdx.y;
    int na = fa[b], nt = ta[b];
    int r0 = blockIdx.x * 32;
    if (r0 >= na || nt == 0) return;
    int w = threadIdx.x >> 5, lane = threadIdx.x & 31;
    const float* Lb = logits + (size_t)b * NN * MM;
    float*       Eb = g_E    + (size_t)b * NN * MM;
    for (int rr = w; rr < 32; rr += 8) {
        int r = r0 + rr;
        if (r >= na) continue;
        float acc = 0.f;
        #pragma unroll 4
        for (int c = lane; c < nt; c += 32) {
            float e = __expf(Lb[r * MM + c]);   // tau = 1
            Eb[r * MM + c] = e;
            acc += e;
        }
        acc = warp_sum(acc);
        if (lane == 0) g_rsum[b * NN + r] = 1.0f / acc;
    }
}

// Row-softmax pass: E' = exp(E * rsum[r]); csum[c] = 1/sum_r E'.
// Column strips of 32 (strip spans all active rows -> colsum local-complete).
__global__ void rownorm_kernel(const int* __restrict__ fa,
                               const int* __restrict__ ta) {
    int b = blockIdx.y;
    int na = fa[b], nt = ta[b];
    int c0 = blockIdx.x * 32;
    if (c0 >= nt || na == 0) return;
    int w = threadIdx.x >> 5, lane = threadIdx.x & 31;
    int c = c0 + lane;
    bool cv = (c < nt);
    float*       Eb = g_E    + (size_t)b * NN * MM;
    const float* rs = g_rsum + b * NN;
    float acc = 0.f;
    if (cv) {
        #pragma unroll 4
        for (int r = w; r < na; r += 8) {
            float inv = rs[r];                  // broadcast load
            float e   = Eb[r * MM + c];
            float e2  = __expf(e * inv);
            Eb[r * MM + c] = e2;
            acc += e2;
        }
    }
    __shared__ float s[8][32];
    s[w][lane] = acc;
    __syncthreads();
    if (w == 0) {
        float t = s[0][lane];
        #pragma unroll
        for (int k = 1; k < 8; k++) t += s[k][lane];
        if (cv) g_csum[b * MM + c] = 1.0f / t;
    }
}

// Col-softmax pass: E' = exp(E * csum[c]); rsum[r] = 1/sum_c E'.
// Row strips of 32 (strip spans all active cols -> rowsum local-complete).
__global__ void colnorm_kernel(const int* __restrict__ fa,
                               const int* __restrict__ ta) {
    int b = blockIdx.y;
    int na = fa[b], nt = ta[b];
    int r0 = blockIdx.x * 32;
    if (r0 >= na || nt == 0) return;
    int w = threadIdx.x >> 5, lane = threadIdx.x & 31;
    float*       Eb = g_E    + (size_t)b * NN * MM;
    const float* cs = g_csum + b * MM;
    for (int rr = w; rr < 32; rr += 8) {
        int r = r0 + rr;
        if (r >= na) continue;
        float acc = 0.f;
        #pragma unroll 4
        for (int c = lane; c < nt; c += 32) {
            float e  = Eb[r * MM + c];
            float e2 = __expf(e * cs[c]);
            Eb[r * MM + c] = e2;
            acc += e2;
        }
        acc = warp_sum(acc);
        if (lane == 0) g_rsum[b * NN + r] = 1.0f / acc;
    }
}

// Final col-softmax (iteration 5, axis=1): out = E * csum[c] inside mask, 0 outside.
// Covers ALL rows/cols (writes the zeros too). Row strips of 32.
__global__ void finalize_kernel(float* __restrict__ out,
                                const int* __restrict__ fa,
                                const int* __restrict__ ta) {
    int b = blockIdx.y;
    int na = fa[b], nt = ta[b];
    int r0 = blockIdx.x * 32;
    int w = threadIdx.x >> 5, lane = threadIdx.x & 31;
    const float* Eb = g_E    + (size_t)b * NN * MM;
    const float* cs = g_csum + b * MM;
    float*       Ob = out    + (size_t)b * NN * MM;
    for (int rr = w; rr < 32; rr += 8) {
        int r = r0 + rr;
        bool rv = (r < na);
        #pragma unroll 4
        for (int c = lane; c < MM; c += 32) {
            float v = 0.f;
            if (rv && c < nt) v = Eb[r * MM + c] * cs[c];
            Ob[r * MM + c] = v;
        }
    }
}

extern "C" void kernel_launch(void* const* d_in, const int* in_sizes, int n_in,
                              void* d_out, int out_size) {
    const float* logits = (const float*)d_in[0];
    const int*   fa     = (const int*)d_in[1];   // free_agents_num -> valid rows (N)
    const int*   ta     = (const int*)d_in[2];   // tasks_num       -> valid cols (M)
    float*       out    = (float*)d_out;

    dim3 grid(16, BB);
    dim3 block(256);

    // init -> rowsum0
    init_kernel<<<grid, block>>>(logits, fa, ta);
    // 5 iterations of (row softmax, col softmax); last col softmax is finalize.
    for (int i = 0; i < 5; i++) {
        rownorm_kernel<<<grid, block>>>(fa, ta);
        if (i < 4) colnorm_kernel<<<grid, block>>>(fa, ta);
    }
    finalize_kernel<<<grid, block>>>(out, fa, ta);
}